// round 1
// baseline (speedup 1.0000x reference)
#include <cuda_runtime.h>
#include <cuda_bf16.h>
#include <math.h>

#define PN 20
#define D4 64
#define BIGF 1e10f

__global__ __launch_bounds__(256, 8)
void spf_kernel(const float* __restrict__ points,
                const float* __restrict__ mask,
                const float* __restrict__ W_rel,   // [3,64]
                const float* __restrict__ b_rel,   // [64]
                const float* __restrict__ W_dist,  // [1,64]
                const float* __restrict__ b_dist,  // [64]
                const float* __restrict__ emb_count, // [50,64]
                const float* __restrict__ W_den,   // [1,64]
                const float* __restrict__ b_den,   // [64]
                float* __restrict__ out)           // [B,20,256]
{
    __shared__ float sp[PN * 3];     // points
    __shared__ float sm[PN];         // mask
    __shared__ float sr[PN * 3];     // rel
    __shared__ float scd[PN];        // ||rel||
    __shared__ float sdn[PN];        // density
    // weight pool: [0,192)=W_rel, [192,256)=b_rel, [256,320)=W_dist,
    // [320,384)=b_dist, [384,448)=W_den, [448,512)=b_den
    __shared__ float sw[512];
    __shared__ float semb[D4];       // emb_count[nv] row
    __shared__ float sc[3];          // centroid
    __shared__ int   snv;            // raw valid count

    const int b = blockIdx.x;
    const int t = threadIdx.x;

    // ---- stage per-batch inputs ----
    if (t < PN * 3) {
        sp[t] = points[(size_t)b * (PN * 3) + t];
    } else if (t >= 64 && t < 64 + PN) {
        sm[t - 64] = mask[(size_t)b * PN + (t - 64)];
    }
    // ---- stage weights (batch-independent, L2-resident) ----
    #pragma unroll
    for (int i = t; i < 512; i += 256) {
        const float* src;
        int off;
        if (i < 192)      { src = W_rel;  off = i; }
        else if (i < 256) { src = b_rel;  off = i - 192; }
        else if (i < 320) { src = W_dist; off = i - 256; }
        else if (i < 384) { src = b_dist; off = i - 320; }
        else if (i < 448) { src = W_den;  off = i - 384; }
        else              { src = b_den;  off = i - 448; }
        sw[i] = src[off];
    }
    __syncthreads();

    // ---- valid count + centroid (20 elems, serial on thread 0) ----
    if (t == 0) {
        float nv = 0.f, cx = 0.f, cy = 0.f, cz = 0.f;
        #pragma unroll
        for (int j = 0; j < PN; j++) {
            float m = sm[j];
            nv += m;
            cx += sp[j * 3 + 0] * m;
            cy += sp[j * 3 + 1] * m;
            cz += sp[j * 3 + 2] * m;
        }
        int nvi = (int)(nv + 0.5f);
        int nvc = nvi < 1 ? 1 : nvi;
        float inv = 1.f / (float)nvc;
        sc[0] = cx * inv; sc[1] = cy * inv; sc[2] = cz * inv;
        snv = nvi;
    }
    __syncthreads();

    const int nvi = snv;
    const int nvc = nvi < 1 ? 1 : nvi;

    if (t < PN) {
        // ---- rel, cdist, local density (one thread per point) ----
        float px = sp[t * 3 + 0], py = sp[t * 3 + 1], pz = sp[t * 3 + 2];
        float rx = px - sc[0], ry = py - sc[1], rz = pz - sc[2];
        sr[t * 3 + 0] = rx; sr[t * 3 + 1] = ry; sr[t * 3 + 2] = rz;
        scd[t] = sqrtf(rx * rx + ry * ry + rz * rz);

        float dens = 0.f;
        if (sm[t] > 0.f && nvi > 1) {
            float d0 = BIGF, d1 = BIGF, d2 = BIGF;
            #pragma unroll
            for (int j = 0; j < PN; j++) {
                if (j == t) continue;
                if (sm[j] <= 0.f) continue;
                float dx = px - sp[j * 3 + 0];
                float dy = py - sp[j * 3 + 1];
                float dz = pz - sp[j * 3 + 2];
                float d = sqrtf(fmaxf(dx * dx + dy * dy + dz * dz, 1e-12f));
                if (d < d0)      { d2 = d1; d1 = d0; d0 = d; }
                else if (d < d1) { d2 = d1; d1 = d; }
                else if (d < d2) { d2 = d; }
            }
            int k = nvi - 1;
            if (k > 3) k = 3;
            if (k < 1) k = 1;
            float s = d0;
            if (k > 1) s += d1;
            if (k > 2) s += d2;
            dens = s / (float)k;
        }
        sdn[t] = dens;
    } else if (t >= 64 && t < 64 + D4) {
        // fetch the count-embedding row for this batch (needs snv)
        semb[t - 64] = emb_count[(size_t)nvc * D4 + (t - 64)];
    }
    __syncthreads();

    // ---- emit output: 20*256 floats = 1280 float4; 5 per thread ----
    float4* ob = (float4*)out + (size_t)b * (PN * D4);
    #pragma unroll
    for (int kk = 0; kk < 5; kk++) {
        int idx = t + kk * 256;        // [0,1280)
        int n   = idx >> 6;            // point index
        int j   = idx & 63;            // float4 within the 256-ch row
        int g   = j >> 4;              // feature group
        int lc  = (j & 15) * 4;        // local channel (0..60 step 4)
        float4 o;
        if (g == 0) {
            float rx = sr[n * 3 + 0], ry = sr[n * 3 + 1], rz = sr[n * 3 + 2];
            o.x = fmaf(rx, sw[lc + 0], fmaf(ry, sw[64 + lc + 0], fmaf(rz, sw[128 + lc + 0], sw[192 + lc + 0])));
            o.y = fmaf(rx, sw[lc + 1], fmaf(ry, sw[64 + lc + 1], fmaf(rz, sw[128 + lc + 1], sw[192 + lc + 1])));
            o.z = fmaf(rx, sw[lc + 2], fmaf(ry, sw[64 + lc + 2], fmaf(rz, sw[128 + lc + 2], sw[192 + lc + 2])));
            o.w = fmaf(rx, sw[lc + 3], fmaf(ry, sw[64 + lc + 3], fmaf(rz, sw[128 + lc + 3], sw[192 + lc + 3])));
        } else if (g == 1) {
            float cd = scd[n];
            o.x = fmaf(cd, sw[256 + lc + 0], sw[320 + lc + 0]);
            o.y = fmaf(cd, sw[256 + lc + 1], sw[320 + lc + 1]);
            o.z = fmaf(cd, sw[256 + lc + 2], sw[320 + lc + 2]);
            o.w = fmaf(cd, sw[256 + lc + 3], sw[320 + lc + 3]);
        } else if (g == 2) {
            o.x = semb[lc + 0];
            o.y = semb[lc + 1];
            o.z = semb[lc + 2];
            o.w = semb[lc + 3];
        } else {
            float dn = sdn[n];
            o.x = fmaf(dn, sw[384 + lc + 0], sw[448 + lc + 0]);
            o.y = fmaf(dn, sw[384 + lc + 1], sw[448 + lc + 1]);
            o.z = fmaf(dn, sw[384 + lc + 2], sw[448 + lc + 2]);
            o.w = fmaf(dn, sw[384 + lc + 3], sw[448 + lc + 3]);
        }
        ob[idx] = o;
    }
}

extern "C" void kernel_launch(void* const* d_in, const int* in_sizes, int n_in,
                              void* d_out, int out_size) {
    const float* points    = (const float*)d_in[0];
    const float* mask      = (const float*)d_in[1];
    const float* W_rel     = (const float*)d_in[2];
    const float* b_rel     = (const float*)d_in[3];
    const float* W_dist    = (const float*)d_in[4];
    const float* b_dist    = (const float*)d_in[5];
    const float* emb_count = (const float*)d_in[6];
    const float* W_den     = (const float*)d_in[7];
    const float* b_den     = (const float*)d_in[8];
    float* out = (float*)d_out;

    int B = in_sizes[0] / (PN * 3);
    spf_kernel<<<B, 256>>>(points, mask, W_rel, b_rel, W_dist, b_dist,
                           emb_count, W_den, b_den, out);
}

// round 2
// speedup vs baseline: 1.6810x; 1.6810x over previous
#include <cuda_runtime.h>
#include <cuda_bf16.h>
#include <math.h>

#define PN 20
#define D4 64
#define GB 8          // batches per CTA
#define BIGF 1e10f

__global__ __launch_bounds__(256, 6)
void spf_kernel(const float* __restrict__ points,
                const float* __restrict__ mask,
                const float* __restrict__ W_rel,     // [3,64]
                const float* __restrict__ b_rel,     // [64]
                const float* __restrict__ W_dist,    // [1,64]
                const float* __restrict__ b_dist,    // [64]
                const float* __restrict__ emb_count, // [50,64]
                const float* __restrict__ W_den,     // [1,64]
                const float* __restrict__ b_den,     // [64]
                float* __restrict__ out,             // [B,20,256]
                int B)
{
    __shared__ float sp [GB][PN * 3];  // points
    __shared__ float smk[GB][PN];      // mask
    __shared__ float sr [GB][PN * 3];  // rel
    __shared__ float scd[GB][PN];      // ||rel||
    __shared__ float sdn[GB][PN];      // density
    __shared__ float semb[GB][D4];     // emb_count row per batch
    // [0,192)=W_rel [192,256)=b_rel [256,320)=W_dist [320,384)=b_dist
    // [384,448)=W_den [448,512)=b_den
    __shared__ float sw[512];

    const int t  = threadIdx.x;
    const int b0 = blockIdx.x * GB;

    // ---------- phase 1: stage inputs (coalesced) ----------
    float* spf = &sp[0][0];
    #pragma unroll
    for (int i = t; i < GB * PN * 3; i += 256) {
        int gb = b0 + i / (PN * 3);
        spf[i] = (gb < B) ? points[(size_t)b0 * (PN * 3) + i] : 0.f;
    }
    float* smf = &smk[0][0];
    if (t < GB * PN) {
        int gb = b0 + t / PN;
        smf[t] = (gb < B) ? mask[(size_t)b0 * PN + t] : 0.f;
    }
    #pragma unroll
    for (int i = t; i < 512; i += 256) {
        const float* src; int off;
        if (i < 192)      { src = W_rel;  off = i; }
        else if (i < 256) { src = b_rel;  off = i - 192; }
        else if (i < 320) { src = W_dist; off = i - 256; }
        else if (i < 384) { src = b_dist; off = i - 320; }
        else if (i < 448) { src = W_den;  off = i - 384; }
        else              { src = b_den;  off = i - 448; }
        sw[i] = src[off];
    }
    __syncthreads();

    // ---------- phase 2: warp w computes batch b0+w ----------
    {
        const int w = t >> 5, lane = t & 31;
        float m = 0.f, px = 0.f, py = 0.f, pz = 0.f;
        if (lane < PN) {
            px = sp[w][lane * 3 + 0];
            py = sp[w][lane * 3 + 1];
            pz = sp[w][lane * 3 + 2];
            m  = smk[w][lane];
        }
        float nvf = m, cx = m * px, cy = m * py, cz = m * pz;
        #pragma unroll
        for (int o = 16; o > 0; o >>= 1) {
            nvf += __shfl_xor_sync(0xffffffffu, nvf, o);
            cx  += __shfl_xor_sync(0xffffffffu, cx,  o);
            cy  += __shfl_xor_sync(0xffffffffu, cy,  o);
            cz  += __shfl_xor_sync(0xffffffffu, cz,  o);
        }
        int nvi = (int)(nvf + 0.5f);
        int nvc = nvi < 1 ? 1 : nvi;
        float inv = 1.f / (float)nvc;
        cx *= inv; cy *= inv; cz *= inv;

        if (lane < PN) {
            float rx = px - cx, ry = py - cy, rz = pz - cz;
            sr[w][lane * 3 + 0] = rx;
            sr[w][lane * 3 + 1] = ry;
            sr[w][lane * 3 + 2] = rz;
            scd[w][lane] = sqrtf(rx * rx + ry * ry + rz * rz);

            float dens = 0.f;
            if (m > 0.f && nvi > 1) {
                float d0 = BIGF, d1 = BIGF, d2 = BIGF;
                #pragma unroll
                for (int j = 0; j < PN; j++) {
                    if (j == lane) continue;
                    if (smk[w][j] <= 0.f) continue;
                    float dx = px - sp[w][j * 3 + 0];
                    float dy = py - sp[w][j * 3 + 1];
                    float dz = pz - sp[w][j * 3 + 2];
                    float d = sqrtf(fmaxf(dx * dx + dy * dy + dz * dz, 1e-12f));
                    if (d < d0)      { d2 = d1; d1 = d0; d0 = d; }
                    else if (d < d1) { d2 = d1; d1 = d; }
                    else if (d < d2) { d2 = d; }
                }
                int k = nvi - 1;
                if (k > 3) k = 3;
                float s = d0;
                if (k > 1) s += d1;
                if (k > 2) s += d2;
                dens = s / (float)k;
            }
            sdn[w][lane] = dens;
        }
        // emb_count row for this batch (nvc uniform across warp)
        semb[w][lane]      = emb_count[(size_t)nvc * D4 + lane];
        semb[w][lane + 32] = emb_count[(size_t)nvc * D4 + lane + 32];
    }
    __syncthreads();

    // ---------- phase 3: emit 8 batches * 1280 float4 ----------
    const int j  = t & 63;          // float4 column within 256-ch row
    const int g  = j >> 4;          // feature group (fixed per thread)
    const int lc = (j & 15) * 4;    // local channel
    const int n0 = t >> 6;          // base point index (0..3)
    float4* outBase = (float4*)out;

    if (g == 0) {
        float a0 = sw[lc],       a1 = sw[lc + 1],       a2 = sw[lc + 2],       a3 = sw[lc + 3];
        float e0 = sw[64 + lc],  e1 = sw[64 + lc + 1],  e2 = sw[64 + lc + 2],  e3 = sw[64 + lc + 3];
        float c0 = sw[128 + lc], c1 = sw[128 + lc + 1], c2 = sw[128 + lc + 2], c3 = sw[128 + lc + 3];
        float f0 = sw[192 + lc], f1 = sw[192 + lc + 1], f2 = sw[192 + lc + 2], f3 = sw[192 + lc + 3];
        #pragma unroll
        for (int w = 0; w < GB; w++) {
            if (b0 + w >= B) break;
            float4* ob = outBase + (size_t)(b0 + w) * (PN * D4 / 4) * 4;
            ob = outBase + (size_t)(b0 + w) * 1280;
            #pragma unroll
            for (int kk = 0; kk < 5; kk++) {
                int n = n0 + kk * 4;
                float rx = sr[w][n * 3 + 0], ry = sr[w][n * 3 + 1], rz = sr[w][n * 3 + 2];
                float4 o;
                o.x = fmaf(rx, a0, fmaf(ry, e0, fmaf(rz, c0, f0)));
                o.y = fmaf(rx, a1, fmaf(ry, e1, fmaf(rz, c1, f1)));
                o.z = fmaf(rx, a2, fmaf(ry, e2, fmaf(rz, c2, f2)));
                o.w = fmaf(rx, a3, fmaf(ry, e3, fmaf(rz, c3, f3)));
                __stcs(ob + j + 64 * n, o);
            }
        }
    } else if (g == 1) {
        float a0 = sw[256 + lc], a1 = sw[256 + lc + 1], a2 = sw[256 + lc + 2], a3 = sw[256 + lc + 3];
        float f0 = sw[320 + lc], f1 = sw[320 + lc + 1], f2 = sw[320 + lc + 2], f3 = sw[320 + lc + 3];
        #pragma unroll
        for (int w = 0; w < GB; w++) {
            if (b0 + w >= B) break;
            float4* ob = outBase + (size_t)(b0 + w) * 1280;
            #pragma unroll
            for (int kk = 0; kk < 5; kk++) {
                int n = n0 + kk * 4;
                float cd = scd[w][n];
                float4 o;
                o.x = fmaf(cd, a0, f0);
                o.y = fmaf(cd, a1, f1);
                o.z = fmaf(cd, a2, f2);
                o.w = fmaf(cd, a3, f3);
                __stcs(ob + j + 64 * n, o);
            }
        }
    } else if (g == 2) {
        #pragma unroll
        for (int w = 0; w < GB; w++) {
            if (b0 + w >= B) break;
            float4 v = *((const float4*)&semb[w][lc]);
            float4* ob = outBase + (size_t)(b0 + w) * 1280;
            #pragma unroll
            for (int kk = 0; kk < 5; kk++) {
                int n = n0 + kk * 4;
                __stcs(ob + j + 64 * n, v);
            }
        }
    } else {
        float a0 = sw[384 + lc], a1 = sw[384 + lc + 1], a2 = sw[384 + lc + 2], a3 = sw[384 + lc + 3];
        float f0 = sw[448 + lc], f1 = sw[448 + lc + 1], f2 = sw[448 + lc + 2], f3 = sw[448 + lc + 3];
        #pragma unroll
        for (int w = 0; w < GB; w++) {
            if (b0 + w >= B) break;
            float4* ob = outBase + (size_t)(b0 + w) * 1280;
            #pragma unroll
            for (int kk = 0; kk < 5; kk++) {
                int n = n0 + kk * 4;
                float dn = sdn[w][n];
                float4 o;
                o.x = fmaf(dn, a0, f0);
                o.y = fmaf(dn, a1, f1);
                o.z = fmaf(dn, a2, f2);
                o.w = fmaf(dn, a3, f3);
                __stcs(ob + j + 64 * n, o);
            }
        }
    }
}

extern "C" void kernel_launch(void* const* d_in, const int* in_sizes, int n_in,
                              void* d_out, int out_size) {
    const float* points    = (const float*)d_in[0];
    const float* mask      = (const float*)d_in[1];
    const float* W_rel     = (const float*)d_in[2];
    const float* b_rel     = (const float*)d_in[3];
    const float* W_dist    = (const float*)d_in[4];
    const float* b_dist    = (const float*)d_in[5];
    const float* emb_count = (const float*)d_in[6];
    const float* W_den     = (const float*)d_in[7];
    const float* b_den     = (const float*)d_in[8];
    float* out = (float*)d_out;

    int B = in_sizes[0] / (PN * 3);
    int grid = (B + GB - 1) / GB;
    spf_kernel<<<grid, 256>>>(points, mask, W_rel, b_rel, W_dist, b_dist,
                              emb_count, W_den, b_den, out, B);
}